// round 7
// baseline (speedup 1.0000x reference)
#include <cuda_runtime.h>
#include <cuda_bf16.h>
#include <cstdint>

#define NB    32
#define CIN   256
#define HH    56
#define WW    56
#define KOUT  256
#define NPIX  (HH*WW)        // 3136
#define KDIM  (CIN*9)        // 2304
#define NCHUNK 72            // 2304 / 32 k-chunks

#define MTILE 128            // out channels per CTA
#define NTILE 112            // pixels per CTA (2 rows x 56)

// stage layout (bytes), 64B rows: A hi 128x64, A lo, B hi 112x64, B lo
#define AH_OFF 0
#define AL_OFF 8192
#define BH_OFF 16384
#define BL_OFF 23552
#define STAGE  30720
#define SM_DYN (3*STAGE + 128)   // 92288/CTA -> 2 CTAs/SM

// ---------------- device scratch -------------------------------------------
__device__ __align__(16) __nv_bfloat16 g_whi[KOUT * KDIM];
__device__ __align__(16) __nv_bfloat16 g_wlo[KOUT * KDIM];
__device__ __align__(16) __nv_bfloat16 g_xhi[(size_t)NB * NPIX * CIN];
__device__ __align__(16) __nv_bfloat16 g_xlo[(size_t)NB * NPIX * CIN];

// ---------------- PTX helpers ----------------------------------------------
__device__ __forceinline__ uint32_t smem_u32(const void* p) {
    uint32_t a;
    asm("{ .reg .u64 t; cvta.to.shared.u64 t, %1; cvt.u32.u64 %0, t; }"
        : "=r"(a) : "l"(p));
    return a;
}

#define CP16(dst, src, sz) \
    asm volatile("cp.async.cg.shared.global [%0], [%1], 16, %2;" \
                 :: "r"(dst), "l"(src), "r"(sz) : "memory")
#define CP_COMMIT() asm volatile("cp.async.commit_group;" ::: "memory")
#define CP_WAIT1()  asm volatile("cp.async.wait_group 1;" ::: "memory")
#define CP_WAIT0()  asm volatile("cp.async.wait_group 0;" ::: "memory")

#define LDSM4(r, a) \
    asm volatile("ldmatrix.sync.aligned.m8n8.x4.shared.b16 {%0,%1,%2,%3}, [%4];" \
                 : "=r"((r)[0]),"=r"((r)[1]),"=r"((r)[2]),"=r"((r)[3]) : "r"(a))
#define LDSM2(r, a) \
    asm volatile("ldmatrix.sync.aligned.m8n8.x2.shared.b16 {%0,%1}, [%2];" \
                 : "=r"((r)[0]),"=r"((r)[1]) : "r"(a))

#define MMA(d, a, b) \
    asm volatile("mma.sync.aligned.m16n8k16.row.col.f32.bf16.bf16.f32 " \
                 "{%0,%1,%2,%3}, {%4,%5,%6,%7}, {%8,%9}, {%0,%1,%2,%3};" \
                 : "+f"((d)[0]),"+f"((d)[1]),"+f"((d)[2]),"+f"((d)[3]) \
                 : "r"((a)[0]),"r"((a)[1]),"r"((a)[2]),"r"((a)[3]), \
                   "r"((b)[0]),"r"((b)[1]))

// ---------------- fused prepass ---------------------------------------------
__global__ void prepass_all(const float* __restrict__ x,
                            const float* __restrict__ w) {
    __shared__ float t[32][33];
    const int tx = threadIdx.x, ty = threadIdx.y;   // 32 x 8

    if (blockIdx.z < NB) {
        const int n  = blockIdx.z;
        const int p0 = blockIdx.x * 32;
        const int c0 = blockIdx.y * 32;

        const float* xb = x + ((size_t)n * CIN + c0) * NPIX + p0;
        #pragma unroll
        for (int yy = ty; yy < 32; yy += 8)
            t[yy][tx] = xb[(size_t)yy * NPIX + tx];
        __syncthreads();

        size_t ob = ((size_t)n * NPIX + p0) * CIN + c0;
        #pragma unroll
        for (int yy = ty; yy < 32; yy += 8) {
            float v = t[tx][yy];
            __nv_bfloat16 hi = __float2bfloat16(v);
            __nv_bfloat16 lo = __float2bfloat16(v - __bfloat162float(hi));
            g_xhi[ob + (size_t)yy * CIN + tx] = hi;
            g_xlo[ob + (size_t)yy * CIN + tx] = lo;
        }
    } else {
        const int b = blockIdx.y * gridDim.x + blockIdx.x;   // 0..783
        const int tl = ty * 32 + tx;
        for (int i = b * 256 + tl; i < KOUT * KDIM; i += 784 * 256) {
            int k = i / KDIM, r = i % KDIM;
            int c = r / 9, tap = r % 9;
            float v = w[i];
            __nv_bfloat16 hi = __float2bfloat16(v);
            __nv_bfloat16 lo = __float2bfloat16(v - __bfloat162float(hi));
            int o = k * KDIM + tap * CIN + c;
            g_whi[o] = hi;
            g_wlo[o] = lo;
        }
    }
}

// ---------------- main kernel ------------------------------------------------
__global__ __launch_bounds__(256, 2)
void conv_mma_kernel(const float* __restrict__ bias, float* __restrict__ out)
{
    extern __shared__ __align__(16) char dsm_raw[];

    const int tid = threadIdx.x;
    const int wid = tid >> 5;
    const int L   = tid & 31;
    const int wm  = wid & 3;             // M group (out-ch quarter)
    const int wn  = wid >> 2;            // N group (pixel row)

    const int r0 = blockIdx.x * 2;       // output row base
    const int k0 = blockIdx.y * MTILE;   // out-channel base
    const int n  = blockIdx.z;           // image

    uint32_t raw = smem_u32(dsm_raw);
    uint32_t sm  = (raw + 127u) & ~127u;
    uint32_t bufs[3] = { sm, sm + STAGE, sm + 2 * STAGE };

    // ---- per-lane ldmatrix constants (identical math to R6) ----
    const int arowL = L & 15;
    const int akh   = L >> 4;
    const int j4    = L >> 3;
    const int bprow = wn * 56 + ((j4 >> 1) << 3) + (L & 7);
    const int bpcol = j4 & 1;
    const int bsrow = wn * 56 + 48 + (L & 7);
    const int bscol = j4 & 1;

    // ---- per-thread staging slot constants (chunk-invariant) ----
    // B slots: i = tid + s*256 (valid while i < NTILE*4 = 448)
    // A slots: i = tid + s*256 (both valid: MTILE*4 = 512)
    int prowAbs[2], pcolv[2];
    uint32_t pixBase[2], aBase[2], boff_s[2], aoff_s[2];
    #pragma unroll
    for (int s = 0; s < 2; ++s) {
        const int i = tid + s * 256;
        const int p = i >> 2, v = i & 3;
        const int pr = p / 56, pc = p % 56;       // garbage for invalid slot, unused
        prowAbs[s] = r0 + pr;
        pcolv[s]   = pc;
        pixBase[s] = (uint32_t)((n * NPIX + prowAbs[s] * WW + pc) * CIN + v * 8);
        uint32_t bo = (uint32_t)(p << 6) + (v << 4);
        boff_s[s] = bo ^ ((bo >> 3) & 0x30);
        aBase[s]  = (uint32_t)((k0 + p) * KDIM + v * 8);   // A row index == p
        uint32_t ao = (uint32_t)(p << 6) + (v << 4);
        aoff_s[s] = ao ^ ((ao >> 3) & 0x30);
    }

    uint32_t giB[2], giA[2], szB[2];
    auto setup_tap = [&](int tap) {
        const int kh = tap / 3 - 1, kw = tap % 3 - 1;
        const int shift = (kh * WW + kw) * CIN;
        #pragma unroll
        for (int s = 0; s < 2; ++s) {
            const int r = prowAbs[s] + kh, w = pcolv[s] + kw;
            const bool in = ((unsigned)r < HH) & ((unsigned)w < WW);
            giB[s] = in ? (uint32_t)((int)pixBase[s] + shift) : 0u;
            szB[s] = in ? 16u : 0u;
            giA[s] = aBase[s] + (uint32_t)(tap * CIN);
        }
    };
    auto emitB = [&](uint32_t sb) {
        CP16(sb + BH_OFF + boff_s[0], g_xhi + giB[0], szB[0]);
        CP16(sb + BL_OFF + boff_s[0], g_xlo + giB[0], szB[0]);
        if (tid < 192) {                       // warp-uniform guard
            CP16(sb + BH_OFF + boff_s[1], g_xhi + giB[1], szB[1]);
            CP16(sb + BL_OFF + boff_s[1], g_xlo + giB[1], szB[1]);
        }
    };
    auto emitA = [&](uint32_t sb) {
        #pragma unroll
        for (int s = 0; s < 2; ++s) {
            CP16(sb + AH_OFF + aoff_s[s], g_whi + giA[s], 16u);
            CP16(sb + AL_OFF + aoff_s[s], g_wlo + giA[s], 16u);
        }
    };
    auto advance = [&]() {
        giB[0] += 32; giB[1] += 32; giA[0] += 32; giA[1] += 32;
    };

    float acc[2][7][4];
    #pragma unroll
    for (int mi = 0; mi < 2; ++mi)
        #pragma unroll
        for (int ni = 0; ni < 7; ++ni)
            #pragma unroll
            for (int q = 0; q < 4; ++q)
                acc[mi][ni][q] = 0.0f;

    // ---- prologue: stage chunks 0 and 1 ----
    setup_tap(0);
    emitB(bufs[0]); emitA(bufs[0]); CP_COMMIT(); advance();
    emitB(bufs[1]); emitA(bufs[1]); CP_COMMIT(); advance();

    // ---- main loop: staging interleaved into the MMA stream ----
    int rd = 0, wr = 2;
    #pragma unroll 1
    for (int ch = 0; ch < NCHUNK; ++ch) {
        const int ce = ch + 2;
        const bool de = (ce < NCHUNK);
        if (de && (ce & 7) == 0) setup_tap(ce >> 3);

        if (ch + 1 < NCHUNK) CP_WAIT1();
        else                 CP_WAIT0();
        __syncthreads();

        const uint32_t sb = bufs[rd], wb = bufs[wr];
        const uint32_t sAh = sb + AH_OFF, sAl = sb + AL_OFF;
        const uint32_t sBh = sb + BH_OFF, sBl = sb + BL_OFF;

        #pragma unroll
        for (int ks = 0; ks < 2; ++ks) {
            uint32_t bh[7][2], bl[7][2];
            #pragma unroll
            for (int pi = 0; pi < 3; ++pi) {
                const int row = bprow + pi * 16;
                const int c16 = (ks * 2 + bpcol) ^ ((row >> 1) & 3);
                const uint32_t ao = (uint32_t)(row << 6) + (c16 << 4);
                LDSM4(&bh[pi * 2][0], sBh + ao);
                LDSM4(&bl[pi * 2][0], sBl + ao);
            }
            {
                const int c16 = (ks * 2 + bscol) ^ ((bsrow >> 1) & 3);
                const uint32_t ao = (uint32_t)(bsrow << 6) + (c16 << 4);
                LDSM2(bh[6], sBh + ao);
                LDSM2(bl[6], sBl + ao);
            }
            uint32_t ah[2][4], al[2][4];
            #pragma unroll
            for (int mi = 0; mi < 2; ++mi) {
                const int row = wm * 32 + mi * 16 + arowL;
                const int c16 = (ks * 2 + akh) ^ ((row >> 1) & 3);
                const uint32_t ao = (uint32_t)(row << 6) + (c16 << 4);
                LDSM4(ah[mi], sAh + ao);
                LDSM4(al[mi], sAl + ao);
            }

            // interleaved staging for chunk ch+2 (cheap: addresses precomputed)
            if (ks == 0) {
                if (de) emitB(wb);
            } else {
                if (de) { emitA(wb); CP_COMMIT(); advance(); }
            }

            #pragma unroll
            for (int mi = 0; mi < 2; ++mi)
                #pragma unroll
                for (int ni = 0; ni < 7; ++ni) {
                    MMA(acc[mi][ni], ah[mi], bh[ni]);   // hi * hi
                    MMA(acc[mi][ni], ah[mi], bl[ni]);   // hi * lo
                    MMA(acc[mi][ni], al[mi], bh[ni]);   // lo * hi
                }
        }

        rd = (rd == 2) ? 0 : rd + 1;
        wr = (wr == 2) ? 0 : wr + 1;
    }

    // ---- epilogue: bias + store ----
    const int gID = L >> 2;
    const int tig = L & 3;
    const int r   = r0 + wn;
    #pragma unroll
    for (int mi = 0; mi < 2; ++mi) {
        const int kbase = k0 + wm * 32 + mi * 16 + gID;
        const float b0 = bias[kbase];
        const float b1 = bias[kbase + 8];
        float* o0 = out + (((size_t)n * KOUT + kbase)     * HH + r) * WW;
        float* o1 = out + (((size_t)n * KOUT + kbase + 8) * HH + r) * WW;
        #pragma unroll
        for (int ni = 0; ni < 7; ++ni) {
            const int c = ni * 8 + tig * 2;
            float2 v0 = make_float2(acc[mi][ni][0] + b0, acc[mi][ni][1] + b0);
            float2 v1 = make_float2(acc[mi][ni][2] + b1, acc[mi][ni][3] + b1);
            *reinterpret_cast<float2*>(o0 + c) = v0;
            *reinterpret_cast<float2*>(o1 + c) = v1;
        }
    }
}

// ---------------- launch -----------------------------------------------------
extern "C" void kernel_launch(void* const* d_in, const int* in_sizes, int n_in,
                              void* d_out, int out_size)
{
    const float* x    = (const float*)d_in[0];
    const float* wgt  = (const float*)d_in[1];
    const float* bias = (const float*)d_in[2];
    float* out        = (float*)d_out;

    cudaFuncSetAttribute(conv_mma_kernel,
                         cudaFuncAttributeMaxDynamicSharedMemorySize, SM_DYN);

    {
        dim3 g(NPIX / 32, CIN / 32, NB + 1);   // 98 x 8 x 33 (z=32: weights)
        dim3 b(32, 8);
        prepass_all<<<g, b>>>(x, wgt);
    }

    dim3 grid(HH / 2, KOUT / MTILE, NB);   // 28 x 2 x 32 = 1792 CTAs
    conv_mma_kernel<<<grid, 256, SM_DYN>>>(bias, out);
}

// round 8
// speedup vs baseline: 1.3427x; 1.3427x over previous
#include <cuda_runtime.h>
#include <cuda_bf16.h>
#include <cstdint>

#define NB    32
#define CIN   256
#define HH    56
#define WW    56
#define KOUT  256
#define NPIX  (HH*WW)        // 3136
#define KDIM  (CIN*9)        // 2304
#define NCHUNK 72            // 2304 / 32 k-chunks

#define MTILE 128            // out channels per CTA
#define NTILE 112            // pixels per CTA (2 rows x 56)

// stage layout (bytes), 128B k-rows of tf32: A 128x128B, B 112x128B
#define A_OFF  0
#define B_OFF  16384
#define STAGE  30720
#define SM_DYN (3*STAGE + 128)   // 92288/CTA -> 2 CTAs/SM

// ---------------- device scratch -------------------------------------------
__device__ __align__(16) float g_wt[KOUT * KDIM];               // tf32-rounded
__device__ __align__(16) float g_xt[(size_t)NB * NPIX * CIN];   // NHWC tf32

// ---------------- PTX helpers ----------------------------------------------
__device__ __forceinline__ uint32_t smem_u32(const void* p) {
    uint32_t a;
    asm("{ .reg .u64 t; cvta.to.shared.u64 t, %1; cvt.u32.u64 %0, t; }"
        : "=r"(a) : "l"(p));
    return a;
}
__device__ __forceinline__ float to_tf32(float v) {
    uint32_t r;
    asm("cvt.rna.tf32.f32 %0, %1;" : "=r"(r) : "f"(v));
    return __uint_as_float(r);
}

#define CP16(dst, src, sz) \
    asm volatile("cp.async.cg.shared.global [%0], [%1], 16, %2;" \
                 :: "r"(dst), "l"(src), "r"(sz) : "memory")
#define CP_COMMIT() asm volatile("cp.async.commit_group;" ::: "memory")
#define CP_WAIT1()  asm volatile("cp.async.wait_group 1;" ::: "memory")
#define CP_WAIT0()  asm volatile("cp.async.wait_group 0;" ::: "memory")

#define LDSM4(r, a) \
    asm volatile("ldmatrix.sync.aligned.m8n8.x4.shared.b16 {%0,%1,%2,%3}, [%4];" \
                 : "=r"((r)[0]),"=r"((r)[1]),"=r"((r)[2]),"=r"((r)[3]) : "r"(a))
#define LDSM2(r, a) \
    asm volatile("ldmatrix.sync.aligned.m8n8.x2.shared.b16 {%0,%1}, [%2];" \
                 : "=r"((r)[0]),"=r"((r)[1]) : "r"(a))

#define MMAT(d, a, b) \
    asm volatile("mma.sync.aligned.m16n8k8.row.col.f32.tf32.tf32.f32 " \
                 "{%0,%1,%2,%3}, {%4,%5,%6,%7}, {%8,%9}, {%0,%1,%2,%3};" \
                 : "+f"((d)[0]),"+f"((d)[1]),"+f"((d)[2]),"+f"((d)[3]) \
                 : "r"((a)[0]),"r"((a)[1]),"r"((a)[2]),"r"((a)[3]), \
                   "r"((b)[0]),"r"((b)[1]))

// ---------------- fused prepass ---------------------------------------------
// z < NB: x NCHW fp32 -> NHWC tf32 (rna).  z == NB: weights -> tf32, tap-major.
__global__ void prepass_all(const float* __restrict__ x,
                            const float* __restrict__ w) {
    __shared__ float t[32][33];
    const int tx = threadIdx.x, ty = threadIdx.y;   // 32 x 8

    if (blockIdx.z < NB) {
        const int n  = blockIdx.z;
        const int p0 = blockIdx.x * 32;
        const int c0 = blockIdx.y * 32;

        const float* xb = x + ((size_t)n * CIN + c0) * NPIX + p0;
        #pragma unroll
        for (int yy = ty; yy < 32; yy += 8)
            t[yy][tx] = xb[(size_t)yy * NPIX + tx];
        __syncthreads();

        size_t ob = ((size_t)n * NPIX + p0) * CIN + c0;
        #pragma unroll
        for (int yy = ty; yy < 32; yy += 8)
            g_xt[ob + (size_t)yy * CIN + tx] = to_tf32(t[tx][yy]);
    } else {
        const int b = blockIdx.y * gridDim.x + blockIdx.x;   // 0..783
        const int tl = ty * 32 + tx;
        for (int i = b * 256 + tl; i < KOUT * KDIM; i += 784 * 256) {
            int k = i / KDIM, r = i % KDIM;
            int c = r / 9, tap = r % 9;
            g_wt[k * KDIM + tap * CIN + c] = to_tf32(w[i]);
        }
    }
}

// ---------------- main kernel ------------------------------------------------
__global__ __launch_bounds__(256, 2)
void conv_mma_kernel(const float* __restrict__ bias, float* __restrict__ out)
{
    extern __shared__ __align__(16) char dsm_raw[];

    const int tid = threadIdx.x;
    const int wid = tid >> 5;
    const int L   = tid & 31;
    const int wm  = wid & 3;             // M group (out-ch quarter)
    const int wn  = wid >> 2;            // N group (pixel row)

    const int r0 = blockIdx.x * 2;       // output row base
    const int k0 = blockIdx.y * MTILE;   // out-channel base
    const int n  = blockIdx.z;           // image

    uint32_t raw = smem_u32(dsm_raw);
    uint32_t sm  = (raw + 127u) & ~127u;
    uint32_t bufs[3] = { sm, sm + STAGE, sm + 2 * STAGE };

    // ---- per-lane ldmatrix constants (tf32 k8 fragments via b16 ldmatrix) ----
    // A x4: lanes 0-7 mat0(rows+0,kg0) / 8-15 mat1(rows+8,kg0) / 16-23 mat2(rows+0,kg1) / 24-31 mat3(rows+8,kg1)
    const int arowL = ((L >> 3) & 1) * 8 + (L & 7);
    const int akg   = L >> 4;            // k 16B-group parity
    // B x4 (ni pair): lanes 0-7 (ni,kg0) / 8-15 (ni,kg1) / 16-23 (ni+1,kg0) / 24-31 (ni+1,kg1)
    const int bprowL = wn * 56 + ((L >> 4) & 1) * 8 + (L & 7);
    const int bpkg   = (L >> 3) & 1;
    // B leftover ni=6 LDSM2 (lanes 0-15 used)
    const int bsrowL = wn * 56 + 48 + (L & 7);
    const int bskg   = (L >> 3) & 1;

    // ---- per-thread staging slot constants (chunk-invariant) ----
    // B: 112 rows x 8 vec16 = 896 slots; s=0..2 full, s=3 for tid<128
    // A: 128 rows x 8 vec16 = 1024 slots; s=0..3 full
    uint32_t pixBase[4], boff_s[4], aBase[4], aoff_s[4];
    int prowAbs[4], pcolv[4];
    #pragma unroll
    for (int s = 0; s < 4; ++s) {
        const int i = tid + s * 256;
        const int p = i >> 3, v = i & 7;
        prowAbs[s] = r0 + p / 56;
        pcolv[s]   = p % 56;
        pixBase[s] = (uint32_t)((n * NPIX + prowAbs[s] * WW + pcolv[s]) * CIN + v * 4);
        uint32_t bo = (uint32_t)(p << 7) + (v << 4);
        boff_s[s] = bo ^ ((bo >> 3) & 0x70);
        aBase[s]  = (uint32_t)((k0 + p) * KDIM + v * 4);
        aoff_s[s] = bo ^ ((bo >> 3) & 0x70);   // same formula (row index == p)
    }

    uint32_t giB[4], giA[4], szB[4];
    auto setup_tap = [&](int tap) {
        const int kh = tap / 3 - 1, kw = tap % 3 - 1;
        const int shift = (kh * WW + kw) * CIN;
        #pragma unroll
        for (int s = 0; s < 4; ++s) {
            const int r = prowAbs[s] + kh, w = pcolv[s] + kw;
            const bool in = ((unsigned)r < HH) & ((unsigned)w < WW);
            giB[s] = in ? (uint32_t)((int)pixBase[s] + shift) : 0u;
            szB[s] = in ? 16u : 0u;
            giA[s] = aBase[s] + (uint32_t)(tap * CIN);
        }
    };
    auto emitB2 = [&](uint32_t sb, int s0) {   // two B slots
        CP16(sb + B_OFF + boff_s[s0], g_xt + giB[s0], szB[s0]);
        if (s0 + 1 < 3 || tid < 128)
            CP16(sb + B_OFF + boff_s[s0 + 1], g_xt + giB[s0 + 1], szB[s0 + 1]);
    };
    auto emitA2 = [&](uint32_t sb, int s0) {   // two A slots
        CP16(sb + A_OFF + aoff_s[s0],     g_wt + giA[s0],     16u);
        CP16(sb + A_OFF + aoff_s[s0 + 1], g_wt + giA[s0 + 1], 16u);
    };
    auto advance = [&]() {
        #pragma unroll
        for (int s = 0; s < 4; ++s) { giB[s] += 32; giA[s] += 32; }
    };

    float acc[2][7][4];
    #pragma unroll
    for (int mi = 0; mi < 2; ++mi)
        #pragma unroll
        for (int ni = 0; ni < 7; ++ni)
            #pragma unroll
            for (int q = 0; q < 4; ++q)
                acc[mi][ni][q] = 0.0f;

    // ---- prologue: stage chunks 0 and 1 ----
    setup_tap(0);
    emitB2(bufs[0], 0); emitB2(bufs[0], 2); emitA2(bufs[0], 0); emitA2(bufs[0], 2);
    CP_COMMIT(); advance();
    emitB2(bufs[1], 0); emitB2(bufs[1], 2); emitA2(bufs[1], 0); emitA2(bufs[1], 2);
    CP_COMMIT(); advance();

    // ---- main loop ----
    int rd = 0, wr = 2;
    #pragma unroll 1
    for (int ch = 0; ch < NCHUNK; ++ch) {
        const int ce = ch + 2;
        const bool de = (ce < NCHUNK);
        if (de && (ce & 7) == 0) setup_tap(ce >> 3);

        if (ch + 1 < NCHUNK) CP_WAIT1();
        else                 CP_WAIT0();
        __syncthreads();

        const uint32_t sb = bufs[rd], wb = bufs[wr];
        const uint32_t sA = sb + A_OFF, sB = sb + B_OFF;

        #pragma unroll
        for (int ks = 0; ks < 4; ++ks) {        // four k8 steps
            uint32_t bt[7][2];
            #pragma unroll
            for (int pi = 0; pi < 3; ++pi) {    // ni pairs 0-1, 2-3, 4-5
                const int row = bprowL + pi * 16;
                const int c16 = (ks * 2 + bpkg) ^ (row & 7);
                LDSM4(&bt[pi * 2][0], sB + (uint32_t)(row << 7) + (c16 << 4));
            }
            {                                   // ni = 6
                const int c16 = (ks * 2 + bskg) ^ (bsrowL & 7);
                LDSM2(bt[6], sB + (uint32_t)(bsrowL << 7) + (c16 << 4));
            }
            uint32_t at[2][4];
            #pragma unroll
            for (int mi = 0; mi < 2; ++mi) {
                const int row = wm * 32 + mi * 16 + arowL;
                const int c16 = (ks * 2 + akg) ^ (row & 7);
                LDSM4(at[mi], sA + (uint32_t)(row << 7) + (c16 << 4));
            }

            // interleaved staging for chunk ch+2
            if (de) {
                if      (ks == 0) emitB2(wb, 0);
                else if (ks == 1) emitB2(wb, 2);
                else if (ks == 2) emitA2(wb, 0);
                else { emitA2(wb, 2); CP_COMMIT(); advance(); }
            }

            #pragma unroll
            for (int mi = 0; mi < 2; ++mi)
                #pragma unroll
                for (int ni = 0; ni < 7; ++ni)
                    MMAT(acc[mi][ni], at[mi], bt[ni]);
        }

        rd = (rd == 2) ? 0 : rd + 1;
        wr = (wr == 2) ? 0 : wr + 1;
    }

    // ---- epilogue: bias + store ----
    const int gID = L >> 2;
    const int tig = L & 3;
    const int r   = r0 + wn;
    #pragma unroll
    for (int mi = 0; mi < 2; ++mi) {
        const int kbase = k0 + wm * 32 + mi * 16 + gID;
        const float b0 = bias[kbase];
        const float b1 = bias[kbase + 8];
        float* o0 = out + (((size_t)n * KOUT + kbase)     * HH + r) * WW;
        float* o1 = out + (((size_t)n * KOUT + kbase + 8) * HH + r) * WW;
        #pragma unroll
        for (int ni = 0; ni < 7; ++ni) {
            const int c = ni * 8 + tig * 2;
            float2 v0 = make_float2(acc[mi][ni][0] + b0, acc[mi][ni][1] + b0);
            float2 v1 = make_float2(acc[mi][ni][2] + b1, acc[mi][ni][3] + b1);
            *reinterpret_cast<float2*>(o0 + c) = v0;
            *reinterpret_cast<float2*>(o1 + c) = v1;
        }
    }
}

// ---------------- launch -----------------------------------------------------
extern "C" void kernel_launch(void* const* d_in, const int* in_sizes, int n_in,
                              void* d_out, int out_size)
{
    const float* x    = (const float*)d_in[0];
    const float* wgt  = (const float*)d_in[1];
    const float* bias = (const float*)d_in[2];
    float* out        = (float*)d_out;

    cudaFuncSetAttribute(conv_mma_kernel,
                         cudaFuncAttributeMaxDynamicSharedMemorySize, SM_DYN);

    {
        dim3 g(NPIX / 32, CIN / 32, NB + 1);   // 98 x 8 x 33 (z=32: weights)
        dim3 b(32, 8);
        prepass_all<<<g, b>>>(x, wgt);
    }

    dim3 grid(HH / 2, KOUT / MTILE, NB);   // 28 x 2 x 32 = 1792 CTAs
    conv_mma_kernel<<<grid, 256, SM_DYN>>>(bias, out);
}

// round 9
// speedup vs baseline: 1.3542x; 1.0086x over previous
#include <cuda_runtime.h>
#include <cstdint>

#define NB    32
#define CIN   256
#define HH    56
#define WW    56
#define KOUT  256
#define NPIX  (HH*WW)        // 3136
#define KDIM  (CIN*9)        // 2304
#define NCHUNK 72            // 2304 / 32 k-chunks

#define MTILE 128            // out channels per CTA
#define NTILE 112            // pixels per CTA (2 rows x 56)

// stage layout (bytes), 128B k-rows of tf32: A 128x128B, B 112x128B
#define A_OFF  0
#define B_OFF  16384
#define STAGE  30720
#define SM_DYN (3*STAGE + 128)   // 92288/CTA -> 2 CTAs/SM

// ---------------- device scratch -------------------------------------------
__device__ __align__(16) float g_wt[KOUT * KDIM];               // tf32-rounded
__device__ __align__(16) float g_xt[(size_t)NB * NPIX * CIN];   // NHWC tf32

// ---------------- PTX helpers ----------------------------------------------
__device__ __forceinline__ uint32_t smem_u32(const void* p) {
    uint32_t a;
    asm("{ .reg .u64 t; cvta.to.shared.u64 t, %1; cvt.u32.u64 %0, t; }"
        : "=r"(a) : "l"(p));
    return a;
}
__device__ __forceinline__ float to_tf32(float v) {
    uint32_t r;
    asm("cvt.rna.tf32.f32 %0, %1;" : "=r"(r) : "f"(v));
    return __uint_as_float(r);
}

#define CP16(dst, src, sz) \
    asm volatile("cp.async.cg.shared.global [%0], [%1], 16, %2;" \
                 :: "r"(dst), "l"(src), "r"(sz) : "memory")
#define CP_COMMIT() asm volatile("cp.async.commit_group;" ::: "memory")
#define CP_WAIT1()  asm volatile("cp.async.wait_group 1;" ::: "memory")
#define CP_WAIT0()  asm volatile("cp.async.wait_group 0;" ::: "memory")

#define LDSM4(r, a) \
    asm volatile("ldmatrix.sync.aligned.m8n8.x4.shared.b16 {%0,%1,%2,%3}, [%4];" \
                 : "=r"((r)[0]),"=r"((r)[1]),"=r"((r)[2]),"=r"((r)[3]) : "r"(a))
#define LDSM2(r, a) \
    asm volatile("ldmatrix.sync.aligned.m8n8.x2.shared.b16 {%0,%1}, [%2];" \
                 : "=r"((r)[0]),"=r"((r)[1]) : "r"(a))

#define MMAT(d, a, b) \
    asm volatile("mma.sync.aligned.m16n8k8.row.col.f32.tf32.tf32.f32 " \
                 "{%0,%1,%2,%3}, {%4,%5,%6,%7}, {%8,%9}, {%0,%1,%2,%3};" \
                 : "+f"((d)[0]),"+f"((d)[1]),"+f"((d)[2]),"+f"((d)[3]) \
                 : "r"((a)[0]),"r"((a)[1]),"r"((a)[2]),"r"((a)[3]), \
                   "r"((b)[0]),"r"((b)[1]))

// ---------------- fused prepass ---------------------------------------------
__global__ void prepass_all(const float* __restrict__ x,
                            const float* __restrict__ w) {
    __shared__ float t[32][33];
    const int tx = threadIdx.x, ty = threadIdx.y;   // 32 x 8

    if (blockIdx.z < NB) {
        const int n  = blockIdx.z;
        const int p0 = blockIdx.x * 32;
        const int c0 = blockIdx.y * 32;

        const float* xb = x + ((size_t)n * CIN + c0) * NPIX + p0;
        #pragma unroll
        for (int yy = ty; yy < 32; yy += 8)
            t[yy][tx] = xb[(size_t)yy * NPIX + tx];
        __syncthreads();

        size_t ob = ((size_t)n * NPIX + p0) * CIN + c0;
        #pragma unroll
        for (int yy = ty; yy < 32; yy += 8)
            g_xt[ob + (size_t)yy * CIN + tx] = to_tf32(t[tx][yy]);
    } else {
        const int b = blockIdx.y * gridDim.x + blockIdx.x;   // 0..783
        const int tl = ty * 32 + tx;
        for (int i = b * 256 + tl; i < KOUT * KDIM; i += 784 * 256) {
            int k = i / KDIM, r = i % KDIM;
            int c = r / 9, tap = r % 9;
            g_wt[k * KDIM + tap * CIN + c] = to_tf32(w[i]);
        }
    }
}

// ---------------- main kernel ------------------------------------------------
__global__ __launch_bounds__(256, 2)
void conv_mma_kernel(const float* __restrict__ bias, float* __restrict__ out)
{
    extern __shared__ __align__(16) char dsm_raw[];

    const int tid = threadIdx.x;
    const int wid = tid >> 5;
    const int L   = tid & 31;
    const int wm  = wid & 3;             // M group (out-ch quarter)
    const int wn  = wid >> 2;            // N group (pixel row)

    const int r0 = blockIdx.x * 2;       // output row base
    const int k0 = blockIdx.y * MTILE;   // out-channel base
    const int n  = blockIdx.z;           // image

    uint32_t raw = smem_u32(dsm_raw);
    uint32_t sm  = (raw + 127u) & ~127u;
    uint32_t bufs[3] = { sm, sm + STAGE, sm + 2 * STAGE };

    // ---- per-lane ldmatrix constants (tf32 k8 fragments via b16 ldmatrix) ----
    const int arowL = ((L >> 3) & 1) * 8 + (L & 7);
    const int akg   = L >> 4;            // A k 16B-group parity
    const int bprowL = wn * 56 + ((L >> 4) & 1) * 8 + (L & 7);
    const int bpkg   = (L >> 3) & 1;
    const int bsrowL = wn * 56 + 48 + (L & 7);
    const int bskg   = (L >> 3) & 1;

    // ---- persistent staging state: 9 regs only ----
    uint32_t giB[4], giA[4], szmask;

    // everything else recomputed (pure functions of tid / tap)
    auto setup_tap = [&](int tap) {
        const int kh = tap / 3 - 1, kw = tap % 3 - 1;
        uint32_t m = 0;
        #pragma unroll
        for (int s = 0; s < 4; ++s) {
            const int i = tid + s * 256;
            const int p = i >> 3, v = i & 7;
            const int r = r0 + p / 56 + kh;
            const int w = p % 56 + kw;
            const bool in = ((unsigned)r < HH) & ((unsigned)w < WW);
            giB[s] = in ? (uint32_t)((n * NPIX + r * WW + w) * CIN + v * 4) : 0u;
            if (in) m |= (1u << s);
            giA[s] = (uint32_t)((k0 + i >> 3) * 0 + (k0 + p) * KDIM + tap * CIN + v * 4);
        }
        szmask = m;
    };
    auto slot_off = [&](int s) -> uint32_t {   // swizzled smem offset for slot s
        const int i = tid + s * 256;
        const int p = i >> 3, v = i & 7;
        uint32_t bo = (uint32_t)(p << 7) + (v << 4);
        return bo ^ ((bo >> 3) & 0x70);
    };
    auto emitB2 = [&](uint32_t sb, int s0) {
        #pragma unroll
        for (int ss = s0; ss < s0 + 2; ++ss) {
            const uint32_t sz = ((szmask >> ss) & 1u) * 16u;
            if (ss < 3 || tid < 128)
                CP16(sb + B_OFF + slot_off(ss), g_xt + giB[ss], sz);
        }
    };
    auto emitA2 = [&](uint32_t sb, int s0) {
        #pragma unroll
        for (int ss = s0; ss < s0 + 2; ++ss)
            CP16(sb + A_OFF + slot_off(ss), g_wt + giA[ss], 16u);
    };
    auto advance = [&]() {
        #pragma unroll
        for (int s = 0; s < 4; ++s) { giB[s] += 32; giA[s] += 32; }
    };

    float acc[2][7][4];
    #pragma unroll
    for (int mi = 0; mi < 2; ++mi)
        #pragma unroll
        for (int ni = 0; ni < 7; ++ni)
            #pragma unroll
            for (int q = 0; q < 4; ++q)
                acc[mi][ni][q] = 0.0f;

    // ---- prologue: stage chunks 0 and 1 ----
    setup_tap(0);
    emitB2(bufs[0], 0); emitB2(bufs[0], 2); emitA2(bufs[0], 0); emitA2(bufs[0], 2);
    CP_COMMIT(); advance();
    emitB2(bufs[1], 0); emitB2(bufs[1], 2); emitA2(bufs[1], 0); emitA2(bufs[1], 2);
    CP_COMMIT(); advance();

    // ---- main loop ----
    int rd = 0, wr = 2;
    #pragma unroll 1
    for (int ch = 0; ch < NCHUNK; ++ch) {
        const int ce = ch + 2;
        const bool de = (ce < NCHUNK);
        if (de && (ce & 7) == 0) setup_tap(ce >> 3);

        if (ch + 1 < NCHUNK) CP_WAIT1();
        else                 CP_WAIT0();
        __syncthreads();

        const uint32_t sb = bufs[rd], wb = bufs[wr];
        const uint32_t sA = sb + A_OFF, sB = sb + B_OFF;

        #pragma unroll
        for (int ks = 0; ks < 4; ++ks) {        // four k8 steps
            uint32_t bt[7][2];
            #pragma unroll
            for (int pi = 0; pi < 3; ++pi) {    // ni pairs 0-1, 2-3, 4-5
                const int row = bprowL + pi * 16;
                const int c16 = (ks * 2 + bpkg) ^ (row & 7);
                LDSM4(&bt[pi * 2][0], sB + (uint32_t)(row << 7) + (c16 << 4));
            }
            {                                   // ni = 6
                const int c16 = (ks * 2 + bskg) ^ (bsrowL & 7);
                LDSM2(bt[6], sB + (uint32_t)(bsrowL << 7) + (c16 << 4));
            }
            uint32_t at[2][4];
            #pragma unroll
            for (int mi = 0; mi < 2; ++mi) {
                const int row = wm * 32 + mi * 16 + arowL;
                const int c16 = (ks * 2 + akg) ^ (row & 7);
                LDSM4(at[mi], sA + (uint32_t)(row << 7) + (c16 << 4));
            }

            // interleaved staging for chunk ch+2
            if (de) {
                if      (ks == 0) emitB2(wb, 0);
                else if (ks == 1) emitB2(wb, 2);
                else if (ks == 2) emitA2(wb, 0);
                else { emitA2(wb, 2); CP_COMMIT(); advance(); }
            }

            #pragma unroll
            for (int mi = 0; mi < 2; ++mi)
                #pragma unroll
                for (int ni = 0; ni < 7; ++ni)
                    MMAT(acc[mi][ni], at[mi], bt[ni]);
        }

        rd = (rd == 2) ? 0 : rd + 1;
        wr = (wr == 2) ? 0 : wr + 1;
    }

    // ---- epilogue: bias + store ----
    const int gID = L >> 2;
    const int tig = L & 3;
    const int r   = r0 + wn;
    #pragma unroll
    for (int mi = 0; mi < 2; ++mi) {
        const int kbase = k0 + wm * 32 + mi * 16 + gID;
        const float b0 = bias[kbase];
        const float b1 = bias[kbase + 8];
        float* o0 = out + (((size_t)n * KOUT + kbase)     * HH + r) * WW;
        float* o1 = out + (((size_t)n * KOUT + kbase + 8) * HH + r) * WW;
        #pragma unroll
        for (int ni = 0; ni < 7; ++ni) {
            const int c = ni * 8 + tig * 2;
            float2 v0 = make_float2(acc[mi][ni][0] + b0, acc[mi][ni][1] + b0);
            float2 v1 = make_float2(acc[mi][ni][2] + b1, acc[mi][ni][3] + b1);
            *reinterpret_cast<float2*>(o0 + c) = v0;
            *reinterpret_cast<float2*>(o1 + c) = v1;
        }
    }
}

// ---------------- launch -----------------------------------------------------
extern "C" void kernel_launch(void* const* d_in, const int* in_sizes, int n_in,
                              void* d_out, int out_size)
{
    const float* x    = (const float*)d_in[0];
    const float* wgt  = (const float*)d_in[1];
    const float* bias = (const float*)d_in[2];
    float* out        = (float*)d_out;

    cudaFuncSetAttribute(conv_mma_kernel,
                         cudaFuncAttributeMaxDynamicSharedMemorySize, SM_DYN);

    {
        dim3 g(NPIX / 32, CIN / 32, NB + 1);   // 98 x 8 x 33 (z=32: weights)
        dim3 b(32, 8);
        prepass_all<<<g, b>>>(x, wgt);
    }

    dim3 grid(HH / 2, KOUT / MTILE, NB);   // 28 x 2 x 32 = 1792 CTAs
    conv_mma_kernel<<<grid, 256, SM_DYN>>>(bias, out);
}